// round 16
// baseline (speedup 1.0000x reference)
#include <cuda_runtime.h>
#include <cuda_bf16.h>
#include <math.h>
#include <stdint.h>

// Problem constants
#define BB 4
#define TT 1024
#define CC 2048
#define HH 16
#define DD 128
#define MM (BB*TT)          // 4096
#define KK CC               // 2048
#define N_QKV (3*CC)        // 6144
#define N_PROJ CC           // 2048
#define ATTN_SCALE 0.088388347648318447f  // 1/sqrt(128)
#define MASK_NEG (-1.0e30f)

// Device-global scratch (no runtime allocation)
__device__ __nv_bfloat16 g_wa_bf[(size_t)N_QKV*KK];
__device__ __nv_bfloat16 g_wp_bf[(size_t)N_PROJ*KK];
__device__ __nv_bfloat16 g_xhi[(size_t)MM*KK];
__device__ __nv_bfloat16 g_xlo[(size_t)MM*KK];
__device__ __nv_bfloat16 g_yhi[(size_t)MM*KK];
__device__ __nv_bfloat16 g_ylo[(size_t)MM*KK];
// q/k in [B,H,T,D]; V stored TRANSPOSED [B,H,D,T]; bf16 hi/lo pairs
__device__ __nv_bfloat16 g_qhi[(size_t)BB*HH*TT*DD];
__device__ __nv_bfloat16 g_qlo[(size_t)BB*HH*TT*DD];
__device__ __nv_bfloat16 g_khi[(size_t)BB*HH*TT*DD];
__device__ __nv_bfloat16 g_klo[(size_t)BB*HH*TT*DD];
__device__ __nv_bfloat16 g_vThi[(size_t)BB*HH*DD*TT];
__device__ __nv_bfloat16 g_vTlo[(size_t)BB*HH*DD*TT];
__device__ float g_bias_a[N_QKV];
__device__ float g_bias_p[N_PROJ];
__device__ int g_flag[4];   // 0:wa 1:wp 2:ba 3:bp ; 0=i8,1=i32,2=f32

// ---------------------------------------------------------------------------
// dtype detection (harness promotes int8 arrays to int32/f32 storage)
// ---------------------------------------------------------------------------
__device__ int detect_words(const unsigned int* w, int nwords)
{
    bool i32 = true, f32 = true;
    for (int i = 0; i < nwords; ++i) {
        unsigned int v = w[i];
        if (!(v < 0x80u || v >= 0xFFFFFF80u)) i32 = false;
        float f = __uint_as_float(v);
        if (!(fabsf(f) <= 128.0f && f == truncf(f))) f32 = false;
        if (!i32 && !f32) break;
    }
    return i32 ? 1 : (f32 ? 2 : 0);
}

__global__ void detect_kernel(const void* wa, const void* wp,
                              const void* ba, const void* bp)
{
    const int t = threadIdx.x;
    if (t == 0) g_flag[0] = detect_words((const unsigned int*)wa, 256);
    if (t == 1) g_flag[1] = detect_words((const unsigned int*)wp, 256);
    if (t == 2) g_flag[2] = detect_words((const unsigned int*)ba, 256);
    if (t == 3) g_flag[3] = detect_words((const unsigned int*)bp, 256);
}

__device__ __forceinline__ int load_qval(const void* src, int f, size_t i)
{
    if (f == 1) return ((const int*)src)[i];
    if (f == 2) return __float2int_rn(((const float*)src)[i]);
    return (int)((const signed char*)src)[i];
}

// Fused prep: wa->bf16, x->hi/lo, biases->float
__global__ void prep_all(const void* wa, const float* __restrict__ x,
                         const void* ba, const void* bp,
                         const float* s_ba, const float* s_bp)
{
    const int bid = blockIdx.x;
    const int tid = threadIdx.x;
    if (bid < 1024) {
        const int f = g_flag[0];
        const size_t n = (size_t)N_QKV*KK;
        const size_t stride = 1024*256;
        for (size_t i = (size_t)bid*256 + tid; i < n; i += stride)
            g_wa_bf[i] = __float2bfloat16_rn((float)load_qval(wa, f, i));
    } else if (bid < 2048) {
        const size_t n = (size_t)MM*KK;
        const size_t stride = 1024*256;
        for (size_t i = (size_t)(bid-1024)*256 + tid; i < n; i += stride) {
            float v = x[i];
            __nv_bfloat16 h = __float2bfloat16_rn(v);
            g_xhi[i] = h;
            g_xlo[i] = __float2bfloat16_rn(v - __bfloat162float(h));
        }
    } else if (bid == 2048) {
        const int f = g_flag[2];
        const float sb = s_ba[0];
        for (int i = tid; i < N_QKV; i += 256)
            g_bias_a[i] = sb * (float)load_qval(ba, f, i);
    } else {
        const int f = g_flag[3];
        const float sb = s_bp[0];
        for (int i = tid; i < N_PROJ; i += 256)
            g_bias_p[i] = sb * (float)load_qval(bp, f, i);
    }
}

__global__ void prep_wp(const void* wp)
{
    const int f = g_flag[1];
    const size_t n = (size_t)N_PROJ*KK;
    const size_t stride = (size_t)gridDim.x*blockDim.x;
    for (size_t i = (size_t)blockIdx.x*blockDim.x + threadIdx.x; i < n; i += stride)
        g_wp_bf[i] = __float2bfloat16_rn((float)load_qval(wp, f, i));
}

// ---------------------------------------------------------------------------
// mma / ldsm / cp.async helpers
// ---------------------------------------------------------------------------
__device__ __forceinline__ void ldsm_x4(uint32_t& r0, uint32_t& r1,
                                        uint32_t& r2, uint32_t& r3, uint32_t a)
{
    asm volatile("ldmatrix.sync.aligned.m8n8.x4.shared.b16 {%0,%1,%2,%3}, [%4];"
                 : "=r"(r0), "=r"(r1), "=r"(r2), "=r"(r3) : "r"(a));
}
__device__ __forceinline__ void ldsm_x2(uint32_t& r0, uint32_t& r1, uint32_t a)
{
    asm volatile("ldmatrix.sync.aligned.m8n8.x2.shared.b16 {%0,%1}, [%2];"
                 : "=r"(r0), "=r"(r1) : "r"(a));
}
__device__ __forceinline__ void mma_bf16(float* c, const uint32_t* a,
                                         const uint32_t* b)
{
    asm volatile(
        "mma.sync.aligned.m16n8k16.row.col.f32.bf16.bf16.f32 "
        "{%0,%1,%2,%3},{%4,%5,%6,%7},{%8,%9},{%0,%1,%2,%3};"
        : "+f"(c[0]), "+f"(c[1]), "+f"(c[2]), "+f"(c[3])
        : "r"(a[0]), "r"(a[1]), "r"(a[2]), "r"(a[3]), "r"(b[0]), "r"(b[1]));
}
__device__ __forceinline__ void cp_async16(uint32_t smem_addr, const void* gptr)
{
    asm volatile("cp.async.cg.shared.global [%0], [%1], 16;"
                 :: "r"(smem_addr), "l"(gptr));
}
__device__ __forceinline__ void cp_commit()
{
    asm volatile("cp.async.commit_group;");
}
template<int N>
__device__ __forceinline__ void cp_wait()
{
    asm volatile("cp.async.wait_group %0;" :: "n"(N));
}

// ---------------------------------------------------------------------------
// Tensor-core GEMM, cp.async double-buffered, BK=64, one sync per tile.
// BM=BN=128, 8 warps (2x4).
// MODE 0: epilogue emits q/k bf16 hi/lo (q pre-scaled) + V TRANSPOSED hi/lo.
// MODE 1: fp32 out.
// ---------------------------------------------------------------------------
#define BKG 64
#define APAD 72                         // 64 data + 8 pad (bf16)
#define TILE_B (128*APAD*2)             // 18432 bytes per 128x64 tile
#define BGEMM_SMEM_BYTES (2*3*TILE_B)   // 110592

template<int MODE>
__global__ void __launch_bounds__(256) bgemm_kernel(
    const float* __restrict__ sW,
    float* __restrict__ out)
{
    const __nv_bfloat16* Ahi = (MODE == 0) ? g_xhi : g_yhi;
    const __nv_bfloat16* Alo = (MODE == 0) ? g_xlo : g_ylo;
    const __nv_bfloat16* Bw  = (MODE == 0) ? g_wa_bf : g_wp_bf;
    const float* biasf       = (MODE == 0) ? g_bias_a : g_bias_p;
    const int Nn = (MODE == 0) ? N_QKV : N_PROJ;

    extern __shared__ __nv_bfloat16 sm[];
    const uint32_t s_base = (uint32_t)__cvta_generic_to_shared(sm);
    uint32_t ahi_s[2], alo_s[2], bsh_s[2];
#pragma unroll
    for (int b = 0; b < 2; ++b) {
        ahi_s[b] = s_base + b*3*TILE_B;
        alo_s[b] = ahi_s[b] + TILE_B;
        bsh_s[b] = alo_s[b] + TILE_B;
    }

    const int tid  = threadIdx.x;
    const int bx   = blockIdx.x;
    const int by   = blockIdx.y;
    const int w    = tid >> 5;
    const int lane = tid & 31;
    const int wm   = w >> 2;
    const int wn   = w & 3;

    float acc[4][4][4];
#pragma unroll
    for (int i = 0; i < 4; ++i)
#pragma unroll
        for (int j = 0; j < 4; ++j)
#pragma unroll
            for (int c = 0; c < 4; ++c) acc[i][j][c] = 0.f;

    // fragment addressing
    const int a_row = wm*64 + ((lane >> 3) & 1)*8 + (lane & 7);
    const int a_col = (lane >> 4)*8;
    const int bx4_row = wn*32 + (lane & 7);
    const int bx4_col = (lane >> 3)*8;   // 0,8,16,24 within 32-k window

    // async tile loader: 3 tiles x 1024 uint4; 256 thr x 4 iters each
    auto load_tile = [&](int buf, int kt) {
#pragma unroll
        for (int p = 0; p < 4; ++p) {
            const int idx = tid + p*256;       // 0..1023
            const int row = idx >> 3;
            const int seg = idx & 7;
            const uint32_t soff = (uint32_t)(row*APAD + seg*8)*2;
            const size_t goff = (size_t)(by*128 + row)*KK + kt*BKG + seg*8;
            cp_async16(ahi_s[buf] + soff, Ahi + goff);
            cp_async16(alo_s[buf] + soff, Alo + goff);
            const size_t boff = (size_t)(bx*128 + row)*KK + kt*BKG + seg*8;
            cp_async16(bsh_s[buf] + soff, Bw + boff);
        }
        cp_commit();
    };

    const int NT = KK/BKG;   // 32
    load_tile(0, 0);

    for (int kt = 0; kt < NT; ++kt) {
        const int buf = kt & 1;
        cp_wait<0>();
        __syncthreads();     // tile kt ready; all warps done reading buf^1
        if (kt + 1 < NT) load_tile(buf ^ 1, kt + 1);

#pragma unroll
        for (int kb = 0; kb < 2; ++kb) {       // two 32-k halves
            uint32_t bfr[4][4];
#pragma unroll
            for (int j = 0; j < 4; ++j)
                ldsm_x4(bfr[j][0], bfr[j][1], bfr[j][2], bfr[j][3],
                        bsh_s[buf] +
                        (uint32_t)((bx4_row + j*8)*APAD + kb*32 + bx4_col)*2);
#pragma unroll
            for (int kf = 0; kf < 2; ++kf) {
                const uint32_t kcol = (uint32_t)(kb*32 + kf*16);
#pragma unroll
                for (int i = 0; i < 4; ++i) {
                    uint32_t a[4];
                    const uint32_t ao =
                        (uint32_t)((a_row + i*16)*APAD + kcol + a_col)*2;
                    ldsm_x4(a[0], a[1], a[2], a[3], ahi_s[buf] + ao);
#pragma unroll
                    for (int j = 0; j < 4; ++j)
                        mma_bf16(acc[i][j], a, &bfr[j][kf*2]);
                    ldsm_x4(a[0], a[1], a[2], a[3], alo_s[buf] + ao);
#pragma unroll
                    for (int j = 0; j < 4; ++j)
                        mma_bf16(acc[i][j], a, &bfr[j][kf*2]);
                }
            }
        }
    }

    const float sw = sW[0];
    const int mrow = (lane >> 2);
    const int ncol = 2*(lane & 3);
#pragma unroll
    for (int i = 0; i < 4; ++i) {
#pragma unroll
        for (int j = 0; j < 4; ++j) {
#pragma unroll
            for (int c = 0; c < 4; ++c) {
                const int m = by*128 + wm*64 + i*16 + mrow + ((c >> 1) ? 8 : 0);
                const int n = bx*128 + wn*32 + j*8 + ncol + (c & 1);
                float v = sw * acc[i][j][c] + biasf[n];
                if (MODE == 1) {
                    out[(size_t)m*Nn + n] = v;
                } else {
                    const int which = n >> 11;       // 0:q 1:k 2:v
                    const int cc = n & 2047;
                    const int hh = cc >> 7;
                    const int dd = cc & 127;
                    const int b_ = m >> 10;
                    const int t_ = m & 1023;
                    if (which == 0) v *= ATTN_SCALE;
                    __nv_bfloat16 hi = __float2bfloat16_rn(v);
                    __nv_bfloat16 lo = __float2bfloat16_rn(v - __bfloat162float(hi));
                    if (which == 2) {
                        const size_t offT = ((size_t)(b_*HH + hh)*DD + dd)*TT + t_;
                        g_vThi[offT] = hi; g_vTlo[offT] = lo;
                    } else {
                        const size_t off = (size_t)((b_*HH + hh)*TT + t_)*DD + dd;
                        if (which == 0) { g_qhi[off] = hi; g_qlo[off] = lo; }
                        else            { g_khi[off] = hi; g_klo[off] = lo; }
                    }
                }
            }
        }
    }
}

// ---------------------------------------------------------------------------
// Tensor-core flash attention (unchanged from passing round 13/14).
// Block = (b,h) x 64-q-rows, 128 threads (4 warps).
// ---------------------------------------------------------------------------
#define QSTR 136
#define PSTR 40
#define ATTN_SMEM_BYTES ((2*64*QSTR + 2*32*QSTR + 2*128*PSTR + 2*64*PSTR)*2) // 82944

__global__ void __launch_bounds__(128) attn_mma_kernel()
{
    extern __shared__ __nv_bfloat16 smem[];
    __nv_bfloat16* Qh  = smem;
    __nv_bfloat16* Ql  = Qh  + 64*QSTR;
    __nv_bfloat16* Kh  = Ql  + 64*QSTR;
    __nv_bfloat16* Kl  = Kh  + 32*QSTR;
    __nv_bfloat16* VhT = Kl  + 32*QSTR;
    __nv_bfloat16* VlT = VhT + 128*PSTR;
    __nv_bfloat16* Ph  = VlT + 128*PSTR;
    __nv_bfloat16* Pl  = Ph  + 64*PSTR;

    const int bh = blockIdx.x;
    const int qt = blockIdx.y;
    const int tid = threadIdx.x;
    const int w = tid >> 5;
    const int lane = tid & 31;
    const int l2 = lane & 15;

    {
        const __nv_bfloat16* qh = g_qhi + (size_t)bh*TT*DD + (size_t)qt*64*DD;
        const __nv_bfloat16* ql = g_qlo + (size_t)bh*TT*DD + (size_t)qt*64*DD;
#pragma unroll
        for (int it = 0; it < 8; ++it) {
            const int idx = tid + it*128;
            const int row = idx >> 4, seg = idx & 15;
            *(uint4*)&Qh[row*QSTR + seg*8] = *(const uint4*)(qh + row*128 + seg*8);
            *(uint4*)&Ql[row*QSTR + seg*8] = *(const uint4*)(ql + row*128 + seg*8);
        }
    }

    const uint32_t qh_b  = (uint32_t)__cvta_generic_to_shared(Qh);
    const uint32_t ql_b  = (uint32_t)__cvta_generic_to_shared(Ql);
    const uint32_t kh_b  = (uint32_t)__cvta_generic_to_shared(Kh);
    const uint32_t kl_b  = (uint32_t)__cvta_generic_to_shared(Kl);
    const uint32_t vhT_b = (uint32_t)__cvta_generic_to_shared(VhT);
    const uint32_t vlT_b = (uint32_t)__cvta_generic_to_shared(VlT);
    const uint32_t ph_b  = (uint32_t)__cvta_generic_to_shared(Ph);
    const uint32_t pl_b  = (uint32_t)__cvta_generic_to_shared(Pl);

    const int a_row_q = w*16 + ((lane >> 3) & 1)*8 + (lane & 7);
    const int acolsel = (lane >> 4)*8;
    const int b_row_k = (l2 & 7);
    const int bcolsel = (l2 >> 3)*8;

    float o[16][4];
#pragma unroll
    for (int nf = 0; nf < 16; ++nf)
#pragma unroll
        for (int c = 0; c < 4; ++c) o[nf][c] = 0.f;

    float m_run0 = MASK_NEG, m_run1 = MASK_NEG;
    float l_run0 = 0.f, l_run1 = 0.f;

    const int r0 = lane >> 2;
    const int qcol = 2*(lane & 3);
    const int grow0 = qt*64 + w*16 + r0;
    const int grow1 = grow0 + 8;
    const int nkt = 2*qt + 2;

    for (int kt = 0; kt < nkt; ++kt) {
        __syncthreads();
        {
            const size_t kbase = (size_t)bh*TT*DD + (size_t)kt*32*DD;
#pragma unroll
            for (int it = 0; it < 4; ++it) {
                const int idx = tid + it*128;
                const int row = idx >> 4, seg = idx & 15;
                const size_t go = kbase + row*128 + seg*8;
                *(uint4*)&Kh[row*QSTR + seg*8] = *(const uint4*)(g_khi + go);
                *(uint4*)&Kl[row*QSTR + seg*8] = *(const uint4*)(g_klo + go);
            }
            const size_t vtbase = (size_t)bh*DD*TT + (size_t)kt*32;
#pragma unroll
            for (int it = 0; it < 4; ++it) {
                const int idx = tid + it*128;
                const int row = idx >> 2, seg = idx & 3;
                const size_t go = vtbase + (size_t)row*TT + seg*8;
                *(uint4*)&VhT[row*PSTR + seg*8] = *(const uint4*)(g_vThi + go);
                *(uint4*)&VlT[row*PSTR + seg*8] = *(const uint4*)(g_vTlo + go);
            }
        }
        __syncthreads();

        float s[4][4];
#pragma unroll
        for (int j = 0; j < 4; ++j)
#pragma unroll
            for (int c = 0; c < 4; ++c) s[j][c] = 0.f;

#pragma unroll
        for (int kd = 0; kd < 8; ++kd) {
            const uint32_t aoff = (uint32_t)(a_row_q*QSTR + kd*16 + acolsel)*2;
            uint32_t ah[4], al[4];
            ldsm_x4(ah[0], ah[1], ah[2], ah[3], qh_b + aoff);
            ldsm_x4(al[0], al[1], al[2], al[3], ql_b + aoff);
#pragma unroll
            for (int j = 0; j < 4; ++j) {
                const uint32_t boff = (uint32_t)((j*8 + b_row_k)*QSTR + kd*16 + bcolsel)*2;
                uint32_t bh2[2], bl2[2];
                ldsm_x2(bh2[0], bh2[1], kh_b + boff);
                ldsm_x2(bl2[0], bl2[1], kl_b + boff);
                mma_bf16(s[j], ah, bh2);
                mma_bf16(s[j], ah, bl2);
                mma_bf16(s[j], al, bh2);
            }
        }

        float m0 = MASK_NEG, m1 = MASK_NEG;
#pragma unroll
        for (int j = 0; j < 4; ++j) {
#pragma unroll
            for (int c = 0; c < 4; ++c) {
                const int gcol = kt*32 + j*8 + qcol + (c & 1);
                const int grow = (c < 2) ? grow0 : grow1;
                if (gcol > grow) s[j][c] = MASK_NEG;
            }
            m0 = fmaxf(m0, fmaxf(s[j][0], s[j][1]));
            m1 = fmaxf(m1, fmaxf(s[j][2], s[j][3]));
        }
        m0 = fmaxf(m0, __shfl_xor_sync(0xffffffffu, m0, 1));
        m0 = fmaxf(m0, __shfl_xor_sync(0xffffffffu, m0, 2));
        m1 = fmaxf(m1, __shfl_xor_sync(0xffffffffu, m1, 1));
        m1 = fmaxf(m1, __shfl_xor_sync(0xffffffffu, m1, 2));

        const float mn0 = fmaxf(m_run0, m0);
        const float mn1 = fmaxf(m_run1, m1);
        const float al0 = __expf(m_run0 - mn0);
        const float al1 = __expf(m_run1 - mn1);
        m_run0 = mn0; m_run1 = mn1;

        float ls0 = 0.f, ls1 = 0.f;
#pragma unroll
        for (int j = 0; j < 4; ++j) {
            s[j][0] = __expf(s[j][0] - mn0);
            s[j][1] = __expf(s[j][1] - mn0);
            s[j][2] = __expf(s[j][2] - mn1);
            s[j][3] = __expf(s[j][3] - mn1);
            ls0 += s[j][0] + s[j][1];
            ls1 += s[j][2] + s[j][3];
        }
        ls0 += __shfl_xor_sync(0xffffffffu, ls0, 1);
        ls0 += __shfl_xor_sync(0xffffffffu, ls0, 2);
        ls1 += __shfl_xor_sync(0xffffffffu, ls1, 1);
        ls1 += __shfl_xor_sync(0xffffffffu, ls1, 2);
        l_run0 = l_run0*al0 + ls0;
        l_run1 = l_run1*al1 + ls1;

        const int prow0 = w*16 + r0;
#pragma unroll
        for (int j = 0; j < 4; ++j) {
            const int pc = j*8 + qcol;
            float p0 = s[j][0], p1 = s[j][1];
            __nv_bfloat16 h0 = __float2bfloat16_rn(p0);
            __nv_bfloat16 h1 = __float2bfloat16_rn(p1);
            *(__nv_bfloat162*)&Ph[prow0*PSTR + pc] = __nv_bfloat162(h0, h1);
            *(__nv_bfloat162*)&Pl[prow0*PSTR + pc] = __nv_bfloat162(
                __float2bfloat16_rn(p0 - __bfloat162float(h0)),
                __float2bfloat16_rn(p1 - __bfloat162float(h1)));
            float p2 = s[j][2], p3 = s[j][3];
            __nv_bfloat16 h2 = __float2bfloat16_rn(p2);
            __nv_bfloat16 h3 = __float2bfloat16_rn(p3);
            *(__nv_bfloat162*)&Ph[(prow0+8)*PSTR + pc] = __nv_bfloat162(h2, h3);
            *(__nv_bfloat162*)&Pl[(prow0+8)*PSTR + pc] = __nv_bfloat162(
                __float2bfloat16_rn(p2 - __bfloat162float(h2)),
                __float2bfloat16_rn(p3 - __bfloat162float(h3)));
        }
        __syncwarp();

#pragma unroll
        for (int nf = 0; nf < 16; ++nf) {
            o[nf][0] *= al0; o[nf][1] *= al0;
            o[nf][2] *= al1; o[nf][3] *= al1;
        }

#pragma unroll
        for (int kf = 0; kf < 2; ++kf) {
            const uint32_t paoff = (uint32_t)(a_row_q*PSTR + kf*16 + acolsel)*2;
            uint32_t pah[4], pal[4];
            ldsm_x4(pah[0], pah[1], pah[2], pah[3], ph_b + paoff);
            ldsm_x4(pal[0], pal[1], pal[2], pal[3], pl_b + paoff);
#pragma unroll
            for (int nf = 0; nf < 16; ++nf) {
                const uint32_t boffV =
                    (uint32_t)((nf*8 + b_row_k)*PSTR + kf*16 + bcolsel)*2;
                uint32_t vbh[2], vbl[2];
                ldsm_x2(vbh[0], vbh[1], vhT_b + boffV);
                ldsm_x2(vbl[0], vbl[1], vlT_b + boffV);
                mma_bf16(o[nf], pah, vbh);
                mma_bf16(o[nf], pah, vbl);
                mma_bf16(o[nf], pal, vbh);
            }
        }
        __syncwarp();
    }

    const float li0 = 1.0f / l_run0;
    const float li1 = 1.0f / l_run1;
    const int b_ = bh >> 4;
    const int h_ = bh & 15;
    const int t0 = qt*64 + w*16 + r0;
    const int t1 = t0 + 8;
#pragma unroll
    for (int nf = 0; nf < 16; ++nf) {
        const int dim = nf*8 + qcol;
        {
            float v0 = o[nf][0]*li0, v1 = o[nf][1]*li0;
            __nv_bfloat16 h0 = __float2bfloat16_rn(v0);
            __nv_bfloat16 h1 = __float2bfloat16_rn(v1);
            const size_t off = (size_t)(b_*TT + t0)*CC + h_*DD + dim;
            *(__nv_bfloat162*)&g_yhi[off] = __nv_bfloat162(h0, h1);
            *(__nv_bfloat162*)&g_ylo[off] = __nv_bfloat162(
                __float2bfloat16_rn(v0 - __bfloat162float(h0)),
                __float2bfloat16_rn(v1 - __bfloat162float(h1)));
        }
        {
            float v2 = o[nf][2]*li1, v3 = o[nf][3]*li1;
            __nv_bfloat16 h2 = __float2bfloat16_rn(v2);
            __nv_bfloat16 h3 = __float2bfloat16_rn(v3);
            const size_t off = (size_t)(b_*TT + t1)*CC + h_*DD + dim;
            *(__nv_bfloat162*)&g_yhi[off] = __nv_bfloat162(h2, h3);
            *(__nv_bfloat162*)&g_ylo[off] = __nv_bfloat162(
                __float2bfloat16_rn(v2 - __bfloat162float(h2)),
                __float2bfloat16_rn(v3 - __bfloat162float(h3)));
        }
    }
}

// ---------------------------------------------------------------------------
extern "C" void kernel_launch(void* const* d_in, const int* in_sizes, int n_in,
                              void* d_out, int out_size)
{
    int i_x = -1, i_wa = -1, i_ba = -1, i_wp = -1, i_bp = -1;
    for (int i = 0; i < n_in; ++i) {
        switch (in_sizes[i]) {
            case 8388608:  i_x  = i; break;
            case 12582912: i_wa = i; break;
            case 6144:     i_ba = i; break;
            case 4194304:  i_wp = i; break;
            case 2048:     i_bp = i; break;
            default: break;
        }
    }
    auto find_scale = [&](int start) -> int {
        for (int j = start + 1; j < n_in; ++j)
            if (in_sizes[j] <= 1) return j;
        return -1;
    };
    const int i_swa = find_scale(i_wa);
    const int i_sba = find_scale(i_ba);
    const int i_swp = find_scale(i_wp);
    const int i_sbp = find_scale(i_bp);

    const float* x        = (const float*)d_in[i_x];
    const void*  w_attn_q = d_in[i_wa];
    const float* s_w_attn = (const float*)d_in[i_swa];
    const void*  b_attn_q = d_in[i_ba];
    const float* s_b_attn = (const float*)d_in[i_sba];
    const void*  w_proj_q = d_in[i_wp];
    const float* s_w_proj = (const float*)d_in[i_swp];
    const void*  b_proj_q = d_in[i_bp];
    const float* s_b_proj = (const float*)d_in[i_sbp];
    float* out = (float*)d_out;

    cudaFuncSetAttribute(attn_mma_kernel,
                         cudaFuncAttributeMaxDynamicSharedMemorySize,
                         ATTN_SMEM_BYTES);
    cudaFuncSetAttribute(bgemm_kernel<0>,
                         cudaFuncAttributeMaxDynamicSharedMemorySize,
                         BGEMM_SMEM_BYTES);
    cudaFuncSetAttribute(bgemm_kernel<1>,
                         cudaFuncAttributeMaxDynamicSharedMemorySize,
                         BGEMM_SMEM_BYTES);

    // 0: dtype detect
    detect_kernel<<<1, 4>>>(w_attn_q, w_proj_q, b_attn_q, b_proj_q);
    // 1: fused prep (wa->bf16, x->hi/lo, biases)
    prep_all<<<2050, 256>>>(w_attn_q, x, b_attn_q, b_proj_q, s_b_attn, s_b_proj);
    // 2: wp->bf16
    prep_wp<<<512, 256>>>(w_proj_q);
    // 3: QKV projection -> q/k hi/lo + transposed V (profiled slot)
    {
        dim3 grid(N_QKV/128, MM/128);
        bgemm_kernel<0><<<grid, 256, BGEMM_SMEM_BYTES>>>(s_w_attn, nullptr);
    }
    // 4: tensor-core flash attention -> y bf16 hi/lo
    {
        dim3 grid(BB*HH, TT/64);
        attn_mma_kernel<<<grid, 128, ATTN_SMEM_BYTES>>>();
    }
    // 5: output projection -> d_out (fp32)
    {
        dim3 grid(N_PROJ/128, MM/128);
        bgemm_kernel<1><<<grid, 256, BGEMM_SMEM_BYTES>>>(s_w_proj, out);
    }
}

// round 17
// speedup vs baseline: 1.5385x; 1.5385x over previous
#include <cuda_runtime.h>
#include <cuda_bf16.h>
#include <math.h>
#include <stdint.h>

// Problem constants
#define BB 4
#define TT 1024
#define CC 2048
#define HH 16
#define DD 128
#define MM (BB*TT)          // 4096
#define KK CC               // 2048
#define N_QKV (3*CC)        // 6144
#define N_PROJ CC           // 2048
#define ATTN_SCALE 0.088388347648318447f  // 1/sqrt(128)
#define MASK_NEG (-1.0e30f)

// Device-global scratch (no runtime allocation)
__device__ __nv_bfloat16 g_wa_bf[(size_t)N_QKV*KK];
__device__ __nv_bfloat16 g_wp_bf[(size_t)N_PROJ*KK];
__device__ __nv_bfloat16 g_xhi[(size_t)MM*KK];
__device__ __nv_bfloat16 g_xlo[(size_t)MM*KK];
__device__ __nv_bfloat16 g_yhi[(size_t)MM*KK];
__device__ __nv_bfloat16 g_ylo[(size_t)MM*KK];
// q/k in [B,H,T,D]; V stored TRANSPOSED [B,H,D,T]; bf16 hi/lo pairs
__device__ __nv_bfloat16 g_qhi[(size_t)BB*HH*TT*DD];
__device__ __nv_bfloat16 g_qlo[(size_t)BB*HH*TT*DD];
__device__ __nv_bfloat16 g_khi[(size_t)BB*HH*TT*DD];
__device__ __nv_bfloat16 g_klo[(size_t)BB*HH*TT*DD];
__device__ __nv_bfloat16 g_vThi[(size_t)BB*HH*DD*TT];
__device__ __nv_bfloat16 g_vTlo[(size_t)BB*HH*DD*TT];
__device__ float g_bias_a[N_QKV];
__device__ float g_bias_p[N_PROJ];
__device__ int g_flag[4];   // 0:wa 1:wp 2:ba 3:bp ; 0=i8,1=i32,2=f32

// ---------------------------------------------------------------------------
// dtype detection (harness promotes int8 arrays to int32/f32 storage)
// ---------------------------------------------------------------------------
__device__ int detect_words(const unsigned int* w, int nwords)
{
    bool i32 = true, f32 = true;
    for (int i = 0; i < nwords; ++i) {
        unsigned int v = w[i];
        if (!(v < 0x80u || v >= 0xFFFFFF80u)) i32 = false;
        float f = __uint_as_float(v);
        if (!(fabsf(f) <= 128.0f && f == truncf(f))) f32 = false;
        if (!i32 && !f32) break;
    }
    return i32 ? 1 : (f32 ? 2 : 0);
}

__global__ void detect_kernel(const void* wa, const void* wp,
                              const void* ba, const void* bp)
{
    const int t = threadIdx.x;
    if (t == 0) g_flag[0] = detect_words((const unsigned int*)wa, 256);
    if (t == 1) g_flag[1] = detect_words((const unsigned int*)wp, 256);
    if (t == 2) g_flag[2] = detect_words((const unsigned int*)ba, 256);
    if (t == 3) g_flag[3] = detect_words((const unsigned int*)bp, 256);
}

__device__ __forceinline__ int load_qval(const void* src, int f, size_t i)
{
    if (f == 1) return ((const int*)src)[i];
    if (f == 2) return __float2int_rn(((const float*)src)[i]);
    return (int)((const signed char*)src)[i];
}

// Fused prep: wa->bf16, x->hi/lo, biases->float
__global__ void prep_all(const void* wa, const float* __restrict__ x,
                         const void* ba, const void* bp,
                         const float* s_ba, const float* s_bp)
{
    const int bid = blockIdx.x;
    const int tid = threadIdx.x;
    if (bid < 1024) {
        const int f = g_flag[0];
        const size_t n = (size_t)N_QKV*KK;
        const size_t stride = 1024*256;
        for (size_t i = (size_t)bid*256 + tid; i < n; i += stride)
            g_wa_bf[i] = __float2bfloat16_rn((float)load_qval(wa, f, i));
    } else if (bid < 2048) {
        const size_t n = (size_t)MM*KK;
        const size_t stride = 1024*256;
        for (size_t i = (size_t)(bid-1024)*256 + tid; i < n; i += stride) {
            float v = x[i];
            __nv_bfloat16 h = __float2bfloat16_rn(v);
            g_xhi[i] = h;
            g_xlo[i] = __float2bfloat16_rn(v - __bfloat162float(h));
        }
    } else if (bid == 2048) {
        const int f = g_flag[2];
        const float sb = s_ba[0];
        for (int i = tid; i < N_QKV; i += 256)
            g_bias_a[i] = sb * (float)load_qval(ba, f, i);
    } else {
        const int f = g_flag[3];
        const float sb = s_bp[0];
        for (int i = tid; i < N_PROJ; i += 256)
            g_bias_p[i] = sb * (float)load_qval(bp, f, i);
    }
}

__global__ void prep_wp(const void* wp)
{
    const int f = g_flag[1];
    const size_t n = (size_t)N_PROJ*KK;
    const size_t stride = (size_t)gridDim.x*blockDim.x;
    for (size_t i = (size_t)blockIdx.x*blockDim.x + threadIdx.x; i < n; i += stride)
        g_wp_bf[i] = __float2bfloat16_rn((float)load_qval(wp, f, i));
}

// ---------------------------------------------------------------------------
// mma / ldsm / cp.async helpers
// ---------------------------------------------------------------------------
__device__ __forceinline__ void ldsm_x4(uint32_t& r0, uint32_t& r1,
                                        uint32_t& r2, uint32_t& r3, uint32_t a)
{
    asm volatile("ldmatrix.sync.aligned.m8n8.x4.shared.b16 {%0,%1,%2,%3}, [%4];"
                 : "=r"(r0), "=r"(r1), "=r"(r2), "=r"(r3) : "r"(a));
}
__device__ __forceinline__ void ldsm_x2(uint32_t& r0, uint32_t& r1, uint32_t a)
{
    asm volatile("ldmatrix.sync.aligned.m8n8.x2.shared.b16 {%0,%1}, [%2];"
                 : "=r"(r0), "=r"(r1) : "r"(a));
}
__device__ __forceinline__ void mma_bf16(float* c, const uint32_t* a,
                                         const uint32_t* b)
{
    asm volatile(
        "mma.sync.aligned.m16n8k16.row.col.f32.bf16.bf16.f32 "
        "{%0,%1,%2,%3},{%4,%5,%6,%7},{%8,%9},{%0,%1,%2,%3};"
        : "+f"(c[0]), "+f"(c[1]), "+f"(c[2]), "+f"(c[3])
        : "r"(a[0]), "r"(a[1]), "r"(a[2]), "r"(a[3]), "r"(b[0]), "r"(b[1]));
}
__device__ __forceinline__ void cp_async16(uint32_t smem_addr, const void* gptr)
{
    asm volatile("cp.async.cg.shared.global [%0], [%1], 16;"
                 :: "r"(smem_addr), "l"(gptr));
}
__device__ __forceinline__ void cp_commit()
{
    asm volatile("cp.async.commit_group;");
}
template<int N>
__device__ __forceinline__ void cp_wait()
{
    asm volatile("cp.async.wait_group %0;" :: "n"(N));
}

// ---------------------------------------------------------------------------
// Tensor-core GEMM, cp.async double-buffered, BK=32, ONE sync per tile.
// BM=BN=128, 8 warps (2x4). Smem 61,440B -> 2 CTAs/SM (round-14 occupancy).
// MODE 0: epilogue emits q/k bf16 hi/lo (q pre-scaled) + V TRANSPOSED hi/lo.
// MODE 1: fp32 out.
// ---------------------------------------------------------------------------
#define APAD 40
#define TILE_B (128*APAD*2)            // bytes per 128x32 tile
#define BGEMM_SMEM_BYTES (2*3*TILE_B)  // 61440

template<int MODE>
__global__ void __launch_bounds__(256) bgemm_kernel(
    const float* __restrict__ sW,
    float* __restrict__ out)
{
    const __nv_bfloat16* Ahi = (MODE == 0) ? g_xhi : g_yhi;
    const __nv_bfloat16* Alo = (MODE == 0) ? g_xlo : g_ylo;
    const __nv_bfloat16* Bw  = (MODE == 0) ? g_wa_bf : g_wp_bf;
    const float* biasf       = (MODE == 0) ? g_bias_a : g_bias_p;
    const int Nn = (MODE == 0) ? N_QKV : N_PROJ;

    extern __shared__ __nv_bfloat16 sm[];
    const uint32_t s_base = (uint32_t)__cvta_generic_to_shared(sm);
    uint32_t ahi_s[2], alo_s[2], bsh_s[2];
#pragma unroll
    for (int b = 0; b < 2; ++b) {
        ahi_s[b] = s_base + b*3*TILE_B;
        alo_s[b] = ahi_s[b] + TILE_B;
        bsh_s[b] = alo_s[b] + TILE_B;
    }

    const int tid  = threadIdx.x;
    const int bx   = blockIdx.x;
    const int by   = blockIdx.y;
    const int w    = tid >> 5;
    const int lane = tid & 31;
    const int wm   = w >> 2;
    const int wn   = w & 3;

    float acc[4][4][4];
#pragma unroll
    for (int i = 0; i < 4; ++i)
#pragma unroll
        for (int j = 0; j < 4; ++j)
#pragma unroll
            for (int c = 0; c < 4; ++c) acc[i][j][c] = 0.f;

    // fragment addressing
    const int a_row = wm*64 + ((lane >> 3) & 1)*8 + (lane & 7);
    const int a_col = (lane >> 4)*8;
    const uint32_t a_off = (uint32_t)(a_row*APAD + a_col)*2;
    const int bx4_row = wn*32 + (lane & 7);
    const int bx4_col = (lane >> 3)*8;
    const uint32_t bx4_off = (uint32_t)(bx4_row*APAD + bx4_col)*2;

    // async tile loader
    auto load_tile = [&](int buf, int kt) {
#pragma unroll
        for (int p = 0; p < 2; ++p) {
            const int idx = tid + p*256;
            const int row = idx >> 2;
            const int seg = idx & 3;
            const uint32_t soff = (uint32_t)(row*APAD + seg*8)*2;
            const size_t goff = (size_t)(by*128 + row)*KK + kt*32 + seg*8;
            cp_async16(ahi_s[buf] + soff, Ahi + goff);
            cp_async16(alo_s[buf] + soff, Alo + goff);
            const size_t boff = (size_t)(bx*128 + row)*KK + kt*32 + seg*8;
            cp_async16(bsh_s[buf] + soff, Bw + boff);
        }
        cp_commit();
    };

    const int NT = KK/32;
    load_tile(0, 0);

    for (int kt = 0; kt < NT; ++kt) {
        const int buf = kt & 1;
        cp_wait<0>();        // tile kt data resident
        __syncthreads();     // all warps done reading buf^1 (last iter's mma)
        if (kt + 1 < NT) load_tile(buf ^ 1, kt + 1);

        // B fragments: one x4 per j covers both kf halves
        uint32_t bfr[4][4];
#pragma unroll
        for (int j = 0; j < 4; ++j)
            ldsm_x4(bfr[j][0], bfr[j][1], bfr[j][2], bfr[j][3],
                    bsh_s[buf] + bx4_off + (uint32_t)(j*8*APAD*2));

#pragma unroll
        for (int kf = 0; kf < 2; ++kf) {
            const uint32_t kfb = (uint32_t)(kf*16*2);
#pragma unroll
            for (int i = 0; i < 4; ++i) {
                uint32_t a[4];
                const uint32_t ao = a_off + (uint32_t)(i*16*APAD*2) + kfb;
                ldsm_x4(a[0], a[1], a[2], a[3], ahi_s[buf] + ao);
#pragma unroll
                for (int j = 0; j < 4; ++j) mma_bf16(acc[i][j], a, &bfr[j][kf*2]);
                ldsm_x4(a[0], a[1], a[2], a[3], alo_s[buf] + ao);
#pragma unroll
                for (int j = 0; j < 4; ++j) mma_bf16(acc[i][j], a, &bfr[j][kf*2]);
            }
        }
    }

    const float sw = sW[0];
    const int mrow = (lane >> 2);
    const int ncol = 2*(lane & 3);
#pragma unroll
    for (int i = 0; i < 4; ++i) {
#pragma unroll
        for (int j = 0; j < 4; ++j) {
#pragma unroll
            for (int c = 0; c < 4; ++c) {
                const int m = by*128 + wm*64 + i*16 + mrow + ((c >> 1) ? 8 : 0);
                const int n = bx*128 + wn*32 + j*8 + ncol + (c & 1);
                float v = sw * acc[i][j][c] + biasf[n];
                if (MODE == 1) {
                    out[(size_t)m*Nn + n] = v;
                } else {
                    const int which = n >> 11;       // 0:q 1:k 2:v
                    const int cc = n & 2047;
                    const int hh = cc >> 7;
                    const int dd = cc & 127;
                    const int b_ = m >> 10;
                    const int t_ = m & 1023;
                    if (which == 0) v *= ATTN_SCALE;
                    __nv_bfloat16 hi = __float2bfloat16_rn(v);
                    __nv_bfloat16 lo = __float2bfloat16_rn(v - __bfloat162float(hi));
                    if (which == 2) {
                        const size_t offT = ((size_t)(b_*HH + hh)*DD + dd)*TT + t_;
                        g_vThi[offT] = hi; g_vTlo[offT] = lo;
                    } else {
                        const size_t off = (size_t)((b_*HH + hh)*TT + t_)*DD + dd;
                        if (which == 0) { g_qhi[off] = hi; g_qlo[off] = lo; }
                        else            { g_khi[off] = hi; g_klo[off] = lo; }
                    }
                }
            }
        }
    }
}

// ---------------------------------------------------------------------------
// Tensor-core flash attention (unchanged from passing rounds 13/14).
// Block = (b,h) x 64-q-rows, 128 threads (4 warps).
// ---------------------------------------------------------------------------
#define QSTR 136
#define PSTR 40
#define ATTN_SMEM_BYTES ((2*64*QSTR + 2*32*QSTR + 2*128*PSTR + 2*64*PSTR)*2) // 82944

__global__ void __launch_bounds__(128) attn_mma_kernel()
{
    extern __shared__ __nv_bfloat16 smem[];
    __nv_bfloat16* Qh  = smem;
    __nv_bfloat16* Ql  = Qh  + 64*QSTR;
    __nv_bfloat16* Kh  = Ql  + 64*QSTR;
    __nv_bfloat16* Kl  = Kh  + 32*QSTR;
    __nv_bfloat16* VhT = Kl  + 32*QSTR;
    __nv_bfloat16* VlT = VhT + 128*PSTR;
    __nv_bfloat16* Ph  = VlT + 128*PSTR;
    __nv_bfloat16* Pl  = Ph  + 64*PSTR;

    const int bh = blockIdx.x;
    const int qt = blockIdx.y;
    const int tid = threadIdx.x;
    const int w = tid >> 5;
    const int lane = tid & 31;
    const int l2 = lane & 15;

    {
        const __nv_bfloat16* qh = g_qhi + (size_t)bh*TT*DD + (size_t)qt*64*DD;
        const __nv_bfloat16* ql = g_qlo + (size_t)bh*TT*DD + (size_t)qt*64*DD;
#pragma unroll
        for (int it = 0; it < 8; ++it) {
            const int idx = tid + it*128;
            const int row = idx >> 4, seg = idx & 15;
            *(uint4*)&Qh[row*QSTR + seg*8] = *(const uint4*)(qh + row*128 + seg*8);
            *(uint4*)&Ql[row*QSTR + seg*8] = *(const uint4*)(ql + row*128 + seg*8);
        }
    }

    const uint32_t qh_b  = (uint32_t)__cvta_generic_to_shared(Qh);
    const uint32_t ql_b  = (uint32_t)__cvta_generic_to_shared(Ql);
    const uint32_t kh_b  = (uint32_t)__cvta_generic_to_shared(Kh);
    const uint32_t kl_b  = (uint32_t)__cvta_generic_to_shared(Kl);
    const uint32_t vhT_b = (uint32_t)__cvta_generic_to_shared(VhT);
    const uint32_t vlT_b = (uint32_t)__cvta_generic_to_shared(VlT);
    const uint32_t ph_b  = (uint32_t)__cvta_generic_to_shared(Ph);
    const uint32_t pl_b  = (uint32_t)__cvta_generic_to_shared(Pl);

    const int a_row_q = w*16 + ((lane >> 3) & 1)*8 + (lane & 7);
    const int acolsel = (lane >> 4)*8;
    const int b_row_k = (l2 & 7);
    const int bcolsel = (l2 >> 3)*8;

    float o[16][4];
#pragma unroll
    for (int nf = 0; nf < 16; ++nf)
#pragma unroll
        for (int c = 0; c < 4; ++c) o[nf][c] = 0.f;

    float m_run0 = MASK_NEG, m_run1 = MASK_NEG;
    float l_run0 = 0.f, l_run1 = 0.f;

    const int r0 = lane >> 2;
    const int qcol = 2*(lane & 3);
    const int grow0 = qt*64 + w*16 + r0;
    const int grow1 = grow0 + 8;
    const int nkt = 2*qt + 2;

    for (int kt = 0; kt < nkt; ++kt) {
        __syncthreads();
        {
            const size_t kbase = (size_t)bh*TT*DD + (size_t)kt*32*DD;
#pragma unroll
            for (int it = 0; it < 4; ++it) {
                const int idx = tid + it*128;
                const int row = idx >> 4, seg = idx & 15;
                const size_t go = kbase + row*128 + seg*8;
                *(uint4*)&Kh[row*QSTR + seg*8] = *(const uint4*)(g_khi + go);
                *(uint4*)&Kl[row*QSTR + seg*8] = *(const uint4*)(g_klo + go);
            }
            const size_t vtbase = (size_t)bh*DD*TT + (size_t)kt*32;
#pragma unroll
            for (int it = 0; it < 4; ++it) {
                const int idx = tid + it*128;
                const int row = idx >> 2, seg = idx & 3;
                const size_t go = vtbase + (size_t)row*TT + seg*8;
                *(uint4*)&VhT[row*PSTR + seg*8] = *(const uint4*)(g_vThi + go);
                *(uint4*)&VlT[row*PSTR + seg*8] = *(const uint4*)(g_vTlo + go);
            }
        }
        __syncthreads();

        float s[4][4];
#pragma unroll
        for (int j = 0; j < 4; ++j)
#pragma unroll
            for (int c = 0; c < 4; ++c) s[j][c] = 0.f;

#pragma unroll
        for (int kd = 0; kd < 8; ++kd) {
            const uint32_t aoff = (uint32_t)(a_row_q*QSTR + kd*16 + acolsel)*2;
            uint32_t ah[4], al[4];
            ldsm_x4(ah[0], ah[1], ah[2], ah[3], qh_b + aoff);
            ldsm_x4(al[0], al[1], al[2], al[3], ql_b + aoff);
#pragma unroll
            for (int j = 0; j < 4; ++j) {
                const uint32_t boff = (uint32_t)((j*8 + b_row_k)*QSTR + kd*16 + bcolsel)*2;
                uint32_t bh2[2], bl2[2];
                ldsm_x2(bh2[0], bh2[1], kh_b + boff);
                ldsm_x2(bl2[0], bl2[1], kl_b + boff);
                mma_bf16(s[j], ah, bh2);
                mma_bf16(s[j], ah, bl2);
                mma_bf16(s[j], al, bh2);
            }
        }

        float m0 = MASK_NEG, m1 = MASK_NEG;
#pragma unroll
        for (int j = 0; j < 4; ++j) {
#pragma unroll
            for (int c = 0; c < 4; ++c) {
                const int gcol = kt*32 + j*8 + qcol + (c & 1);
                const int grow = (c < 2) ? grow0 : grow1;
                if (gcol > grow) s[j][c] = MASK_NEG;
            }
            m0 = fmaxf(m0, fmaxf(s[j][0], s[j][1]));
            m1 = fmaxf(m1, fmaxf(s[j][2], s[j][3]));
        }
        m0 = fmaxf(m0, __shfl_xor_sync(0xffffffffu, m0, 1));
        m0 = fmaxf(m0, __shfl_xor_sync(0xffffffffu, m0, 2));
        m1 = fmaxf(m1, __shfl_xor_sync(0xffffffffu, m1, 1));
        m1 = fmaxf(m1, __shfl_xor_sync(0xffffffffu, m1, 2));

        const float mn0 = fmaxf(m_run0, m0);
        const float mn1 = fmaxf(m_run1, m1);
        const float al0 = __expf(m_run0 - mn0);
        const float al1 = __expf(m_run1 - mn1);
        m_run0 = mn0; m_run1 = mn1;

        float ls0 = 0.f, ls1 = 0.f;
#pragma unroll
        for (int j = 0; j < 4; ++j) {
            s[j][0] = __expf(s[j][0] - mn0);
            s[j][1] = __expf(s[j][1] - mn0);
            s[j][2] = __expf(s[j][2] - mn1);
            s[j][3] = __expf(s[j][3] - mn1);
            ls0 += s[j][0] + s[j][1];
            ls1 += s[j][2] + s[j][3];
        }
        ls0 += __shfl_xor_sync(0xffffffffu, ls0, 1);
        ls0 += __shfl_xor_sync(0xffffffffu, ls0, 2);
        ls1 += __shfl_xor_sync(0xffffffffu, ls1, 1);
        ls1 += __shfl_xor_sync(0xffffffffu, ls1, 2);
        l_run0 = l_run0*al0 + ls0;
        l_run1 = l_run1*al1 + ls1;

        const int prow0 = w*16 + r0;
#pragma unroll
        for (int j = 0; j < 4; ++j) {
            const int pc = j*8 + qcol;
            float p0 = s[j][0], p1 = s[j][1];
            __nv_bfloat16 h0 = __float2bfloat16_rn(p0);
            __nv_bfloat16 h1 = __float2bfloat16_rn(p1);
            *(__nv_bfloat162*)&Ph[prow0*PSTR + pc] = __nv_bfloat162(h0, h1);
            *(__nv_bfloat162*)&Pl[prow0*PSTR + pc] = __nv_bfloat162(
                __float2bfloat16_rn(p0 - __bfloat162float(h0)),
                __float2bfloat16_rn(p1 - __bfloat162float(h1)));
            float p2 = s[j][2], p3 = s[j][3];
            __nv_bfloat16 h2 = __float2bfloat16_rn(p2);
            __nv_bfloat16 h3 = __float2bfloat16_rn(p3);
            *(__nv_bfloat162*)&Ph[(prow0+8)*PSTR + pc] = __nv_bfloat162(h2, h3);
            *(__nv_bfloat162*)&Pl[(prow0+8)*PSTR + pc] = __nv_bfloat162(
                __float2bfloat16_rn(p2 - __bfloat162float(h2)),
                __float2bfloat16_rn(p3 - __bfloat162float(h3)));
        }
        __syncwarp();

#pragma unroll
        for (int nf = 0; nf < 16; ++nf) {
            o[nf][0] *= al0; o[nf][1] *= al0;
            o[nf][2] *= al1; o[nf][3] *= al1;
        }

#pragma unroll
        for (int kf = 0; kf < 2; ++kf) {
            const uint32_t paoff = (uint32_t)(a_row_q*PSTR + kf*16 + acolsel)*2;
            uint32_t pah[4], pal[4];
            ldsm_x4(pah[0], pah[1], pah[2], pah[3], ph_b + paoff);
            ldsm_x4(pal[0], pal[1], pal[2], pal[3], pl_b + paoff);
#pragma unroll
            for (int nf = 0; nf < 16; ++nf) {
                const uint32_t boffV =
                    (uint32_t)((nf*8 + b_row_k)*PSTR + kf*16 + bcolsel)*2;
                uint32_t vbh[2], vbl[2];
                ldsm_x2(vbh[0], vbh[1], vhT_b + boffV);
                ldsm_x2(vbl[0], vbl[1], vlT_b + boffV);
                mma_bf16(o[nf], pah, vbh);
                mma_bf16(o[nf], pah, vbl);
                mma_bf16(o[nf], pal, vbh);
            }
        }
        __syncwarp();
    }

    const float li0 = 1.0f / l_run0;
    const float li1 = 1.0f / l_run1;
    const int b_ = bh >> 4;
    const int h_ = bh & 15;
    const int t0 = qt*64 + w*16 + r0;
    const int t1 = t0 + 8;
#pragma unroll
    for (int nf = 0; nf < 16; ++nf) {
        const int dim = nf*8 + qcol;
        {
            float v0 = o[nf][0]*li0, v1 = o[nf][1]*li0;
            __nv_bfloat16 h0 = __float2bfloat16_rn(v0);
            __nv_bfloat16 h1 = __float2bfloat16_rn(v1);
            const size_t off = (size_t)(b_*TT + t0)*CC + h_*DD + dim;
            *(__nv_bfloat162*)&g_yhi[off] = __nv_bfloat162(h0, h1);
            *(__nv_bfloat162*)&g_ylo[off] = __nv_bfloat162(
                __float2bfloat16_rn(v0 - __bfloat162float(h0)),
                __float2bfloat16_rn(v1 - __bfloat162float(h1)));
        }
        {
            float v2 = o[nf][2]*li1, v3 = o[nf][3]*li1;
            __nv_bfloat16 h2 = __float2bfloat16_rn(v2);
            __nv_bfloat16 h3 = __float2bfloat16_rn(v3);
            const size_t off = (size_t)(b_*TT + t1)*CC + h_*DD + dim;
            *(__nv_bfloat162*)&g_yhi[off] = __nv_bfloat162(h2, h3);
            *(__nv_bfloat162*)&g_ylo[off] = __nv_bfloat162(
                __float2bfloat16_rn(v2 - __bfloat162float(h2)),
                __float2bfloat16_rn(v3 - __bfloat162float(h3)));
        }
    }
}

// ---------------------------------------------------------------------------
extern "C" void kernel_launch(void* const* d_in, const int* in_sizes, int n_in,
                              void* d_out, int out_size)
{
    int i_x = -1, i_wa = -1, i_ba = -1, i_wp = -1, i_bp = -1;
    for (int i = 0; i < n_in; ++i) {
        switch (in_sizes[i]) {
            case 8388608:  i_x  = i; break;
            case 12582912: i_wa = i; break;
            case 6144:     i_ba = i; break;
            case 4194304:  i_wp = i; break;
            case 2048:     i_bp = i; break;
            default: break;
        }
    }
    auto find_scale = [&](int start) -> int {
        for (int j = start + 1; j < n_in; ++j)
            if (in_sizes[j] <= 1) return j;
        return -1;
    };
    const int i_swa = find_scale(i_wa);
    const int i_sba = find_scale(i_ba);
    const int i_swp = find_scale(i_wp);
    const int i_sbp = find_scale(i_bp);

    const float* x        = (const float*)d_in[i_x];
    const void*  w_attn_q = d_in[i_wa];
    const float* s_w_attn = (const float*)d_in[i_swa];
    const void*  b_attn_q = d_in[i_ba];
    const float* s_b_attn = (const float*)d_in[i_sba];
    const void*  w_proj_q = d_in[i_wp];
    const float* s_w_proj = (const float*)d_in[i_swp];
    const void*  b_proj_q = d_in[i_bp];
    const float* s_b_proj = (const float*)d_in[i_sbp];
    float* out = (float*)d_out;

    cudaFuncSetAttribute(attn_mma_kernel,
                         cudaFuncAttributeMaxDynamicSharedMemorySize,
                         ATTN_SMEM_BYTES);
    cudaFuncSetAttribute(bgemm_kernel<0>,
                         cudaFuncAttributeMaxDynamicSharedMemorySize,
                         BGEMM_SMEM_BYTES);
    cudaFuncSetAttribute(bgemm_kernel<1>,
                         cudaFuncAttributeMaxDynamicSharedMemorySize,
                         BGEMM_SMEM_BYTES);

    // 0: dtype detect
    detect_kernel<<<1, 4>>>(w_attn_q, w_proj_q, b_attn_q, b_proj_q);
    // 1: fused prep (wa->bf16, x->hi/lo, biases)
    prep_all<<<2050, 256>>>(w_attn_q, x, b_attn_q, b_proj_q, s_b_attn, s_b_proj);
    // 2: wp->bf16
    prep_wp<<<512, 256>>>(w_proj_q);
    // 3: QKV projection -> q/k hi/lo + transposed V (profiled slot)
    {
        dim3 grid(N_QKV/128, MM/128);
        bgemm_kernel<0><<<grid, 256, BGEMM_SMEM_BYTES>>>(s_w_attn, nullptr);
    }
    // 4: tensor-core flash attention -> y bf16 hi/lo
    {
        dim3 grid(BB*HH, TT/64);
        attn_mma_kernel<<<grid, 128, ATTN_SMEM_BYTES>>>();
    }
    // 5: output projection -> d_out (fp32)
    {
        dim3 grid(N_PROJ/128, MM/128);
        bgemm_kernel<1><<<grid, 256, BGEMM_SMEM_BYTES>>>(s_w_proj, out);
    }
}